// round 7
// baseline (speedup 1.0000x reference)
#include <cuda_runtime.h>
#include <cuda_fp16.h>
#include <stdint.h>

namespace {

constexpr int M  = 32;
constexpr int N  = 11008;
constexpr int K  = 4096;
constexpr int NT = 64;               // output channels per CTA
constexpr int KC = 128;              // K elems per chunk
constexpr int NITER = K / KC;        // 32
constexpr int XSTRIDE = KC + 8;      // 136 halves (17x16B rows): conflict-free ldmatrix
constexpr int XBUF_HALVES = M * XSTRIDE;          // 4352
constexpr int SMEM_BYTES  = 2 * XBUF_HALVES * 2;  // 17408

__device__ __forceinline__ void ldsm4(uint32_t r[4], uint32_t a) {
    asm volatile("ldmatrix.sync.aligned.m8n8.x4.shared.b16 {%0,%1,%2,%3}, [%4];"
                 : "=r"(r[0]), "=r"(r[1]), "=r"(r[2]), "=r"(r[3]) : "r"(a));
}
__device__ __forceinline__ void mma16816(float c[4], const uint32_t a[4], const uint32_t b[2]) {
    asm volatile(
        "mma.sync.aligned.m16n8k16.row.col.f32.f16.f16.f32 "
        "{%0,%1,%2,%3}, {%4,%5,%6,%7}, {%8,%9}, {%0,%1,%2,%3};"
        : "+f"(c[0]), "+f"(c[1]), "+f"(c[2]), "+f"(c[3])
        : "r"(a[0]), "r"(a[1]), "r"(a[2]), "r"(a[3]), "r"(b[0]), "r"(b[1]));
}
__device__ __forceinline__ uint32_t h2_u32(__half2 h) {
    return *reinterpret_cast<uint32_t*>(&h);
}
__device__ __forceinline__ uint32_t cvt_i2(uint2 v) {
    return h2_u32(__halves2half2(__int2half_rn((int)v.x), __int2half_rn((int)v.y)));
}
__device__ __forceinline__ uint32_t cvt_f2(uint2 v) {
    return h2_u32(__floats2half2_rn(__uint_as_float(v.x), __uint_as_float(v.y)));
}

__global__ void __launch_bounds__(256, 2)
qlinear_kernel(const float* __restrict__ x, const uint32_t* __restrict__ qw,
               const float* __restrict__ scales, const float* __restrict__ bias,
               float* __restrict__ out)
{
    extern __shared__ __half sm[];

    const int tid  = threadIdx.x;
    const int lane = tid & 31;
    const int warp = tid >> 5;
    const int wn   = warp & 3;    // n16 slot within the 64-wide tile
    const int kg   = warp >> 2;   // k-half of each chunk
    const int o0   = blockIdx.x * NT;

    // ---- uniform dtype probe on qweight words: 0 = int32, 1 = float32 ----
    int mode;
    {
        uint32_t all_int = 1u;
#pragma unroll
        for (int i = 0; i < 8; ++i) {
            uint32_t w = __ldg(qw + i);
            all_int &= ((w + 128u) < 256u) ? 1u : 0u;
        }
        mode = all_int ? 0 : 1;
    }

    // ---- weight fragment pointers (direct-LDG, fragment layout) ----
    const int fr = lane >> 2;          // row within n8 tile
    const int fk = (lane & 3) * 2;     // k pair base
    // base: row (o0 + wn*16 + fr), k (kg*64 + fk)
    const uint32_t* wp = qw + (size_t)(o0 + wn * 16 + fr) * K + kg * 64 + fk;

    // braw[nf*8 + s*2 + h]: raw weight pairs for chunk currently in flight
    uint2 braw[16];
    auto ldw_all = [&](int it) {
        const int kc = it * KC;
#pragma unroll
        for (int nf = 0; nf < 2; ++nf)
#pragma unroll
            for (int s = 0; s < 4; ++s) {
                const uint32_t* p = wp + (size_t)nf * 8 * K + kc + s * 16;
                braw[nf * 8 + s * 2 + 0] = *reinterpret_cast<const uint2*>(p);
                braw[nf * 8 + s * 2 + 1] = *reinterpret_cast<const uint2*>(p + 8);
            }
    };

    // ---- x staging: fp32 -> fp16 smem, double buffered ----
    const int xrow = tid >> 3;         // 0..31
    const int xc4  = tid & 7;
    float4 xr[4];
    auto ldx = [&](int it) {
        const int kc = it * KC;
        const float* src = x + (size_t)xrow * K + kc + xc4 * 4;
#pragma unroll
        for (int p = 0; p < 4; ++p)
            xr[p] = *reinterpret_cast<const float4*>(src + p * 32);
    };
    auto stx = [&](int buf) {
        __half* xb = sm + buf * XBUF_HALVES;
#pragma unroll
        for (int p = 0; p < 4; ++p) {
            uint32_t h01 = h2_u32(__floats2half2_rn(xr[p].x, xr[p].y));
            uint32_t h23 = h2_u32(__floats2half2_rn(xr[p].z, xr[p].w));
            *reinterpret_cast<uint2*>(xb + xrow * XSTRIDE + xc4 * 4 + p * 32)
                = make_uint2(h01, h23);
        }
    };

    // ldmatrix lane->address map for A (x) fragments
    const int rowA = ((lane >> 3) & 1) * 8 + (lane & 7);
    const int colA = (lane >> 4) * 8;
    const uint32_t x0 = (uint32_t)__cvta_generic_to_shared(sm);
    const uint32_t x1 = x0 + XBUF_HALVES * 2;
    const uint32_t aoff0 = ((0 + rowA) * XSTRIDE + colA) * 2;
    const uint32_t aoff1 = ((16 + rowA) * XSTRIDE + colA) * 2;

    float acc[2][2][4];
#pragma unroll
    for (int i = 0; i < 2; ++i)
#pragma unroll
        for (int j = 0; j < 2; ++j)
#pragma unroll
            for (int e = 0; e < 4; ++e) acc[i][j][e] = 0.f;

    // ---- prologue ----
    ldw_all(0);
    ldx(0);
    stx(0);
    __syncthreads();

    // ---- mainloop: rotating weight refill keeps ~4KB/warp of LDG in flight ----
    for (int it = 0; it < NITER; ++it) {
        const bool more = (it + 1 < NITER);
        if (more) ldx(it + 1);

        const uint32_t xbase = (it & 1) ? x1 : x0;
        const int kcn = (it + 1) * KC;

#pragma unroll
        for (int s = 0; s < 4; ++s) {
            const uint32_t koff = (uint32_t)(kg * 64 + s * 16) * 2;
            uint32_t a0[4], a1[4];
            ldsm4(a0, xbase + aoff0 + koff);
            ldsm4(a1, xbase + aoff1 + koff);
#pragma unroll
            for (int nf = 0; nf < 2; ++nf) {
                const int i0 = nf * 8 + s * 2;
                uint32_t b[2];
                if (mode == 0) { b[0] = cvt_i2(braw[i0]); b[1] = cvt_i2(braw[i0 + 1]); }
                else           { b[0] = cvt_f2(braw[i0]); b[1] = cvt_f2(braw[i0 + 1]); }
                if (more) {   // refill this slot for chunk it+1 immediately
                    const uint32_t* p = wp + (size_t)nf * 8 * K + kcn + s * 16;
                    braw[i0]     = *reinterpret_cast<const uint2*>(p);
                    braw[i0 + 1] = *reinterpret_cast<const uint2*>(p + 8);
                }
                mma16816(acc[0][nf], a0, b);
                mma16816(acc[1][nf], a1, b);
            }
        }

        if (more) stx((it + 1) & 1);
        __syncthreads();
    }

    // ---- split-K reduction across kg halves ----
    float* red = reinterpret_cast<float*>(sm);   // 8 KB scratch, x bufs dead
    if (kg == 1) {
#pragma unroll
        for (int i = 0; i < 2; ++i)
#pragma unroll
            for (int j = 0; j < 2; ++j)
#pragma unroll
                for (int e = 0; e < 4; ++e)
                    red[((wn * 32 + lane) * 16) + (i * 2 + j) * 4 + e] = acc[i][j][e];
    }
    __syncthreads();
    if (kg == 0) {
#pragma unroll
        for (int i = 0; i < 2; ++i)
#pragma unroll
            for (int j = 0; j < 2; ++j)
#pragma unroll
                for (int e = 0; e < 4; ++e)
                    acc[i][j][e] += red[((wn * 32 + lane) * 16) + (i * 2 + j) * 4 + e];

        // ---- epilogue: scale + bias (f32), round to fp16 values, store f32 ----
        const int gm = lane >> 2;
        const int gn = (lane & 3) * 2;
#pragma unroll
        for (int nt = 0; nt < 2; ++nt) {
            const int o = o0 + wn * 16 + nt * 8 + gn;
            const float s0 = scales[o];
            const float s1 = scales[o + 1];
            const float b0 = bias[o];
            const float b1 = bias[o + 1];
#pragma unroll
            for (int mt = 0; mt < 2; ++mt) {
                const float* c = acc[mt][nt];
                const int r0 = mt * 16 + gm;
                float2 v0, v1;
                v0.x = __half2float(__float2half_rn(c[0] * s0 + b0));
                v0.y = __half2float(__float2half_rn(c[1] * s1 + b1));
                v1.x = __half2float(__float2half_rn(c[2] * s0 + b0));
                v1.y = __half2float(__float2half_rn(c[3] * s1 + b1));
                *reinterpret_cast<float2*>(out + (size_t)r0 * N + o) = v0;
                *reinterpret_cast<float2*>(out + (size_t)(r0 + 8) * N + o) = v1;
            }
        }
    }
}

} // anonymous namespace

extern "C" void kernel_launch(void* const* d_in, const int* in_sizes, int n_in,
                              void* d_out, int out_size) {
    const float*    x  = reinterpret_cast<const float*>(d_in[0]);
    const uint32_t* qw = reinterpret_cast<const uint32_t*>(d_in[1]);
    const float*    sc = reinterpret_cast<const float*>(d_in[2]);
    const float*    bi = reinterpret_cast<const float*>(d_in[3]);
    float*          o  = reinterpret_cast<float*>(d_out);

    cudaFuncSetAttribute(qlinear_kernel,
                         cudaFuncAttributeMaxDynamicSharedMemorySize, SMEM_BYTES);
    qlinear_kernel<<<N / NT, 256, SMEM_BYTES>>>(x, qw, sc, bi, o);
}

// round 10
// speedup vs baseline: 1.0393x; 1.0393x over previous
#include <cuda_runtime.h>
#include <cuda_fp16.h>
#include <stdint.h>

namespace {

constexpr int M  = 32;
constexpr int N  = 11008;
constexpr int K  = 4096;
constexpr int NT = 64;               // output channels per CTA
constexpr int KC = 64;               // K elems per ring stage
constexpr int NITER  = K / KC;       // 64 (even)
constexpr int STAGES = 6;
constexpr int WTS = 72;              // padded stride in halves (144B rows, conflict-free ldsm)
constexpr int WT_HALVES = NT * WTS;            // 4608
constexpr int XT_HALVES = M  * WTS;            // 2304
constexpr int STAGE_HALVES = WT_HALVES + XT_HALVES;  // 6912 (13824 B)
constexpr int DATA_OFF = 1024;       // bytes reserved for mbarriers at smem front
constexpr int SMEM_BYTES = DATA_OFF + STAGES * STAGE_HALVES * 2;  // 83968

__device__ __forceinline__ void mbar_init(uint32_t a, uint32_t cnt) {
    asm volatile("mbarrier.init.shared.b64 [%0], %1;" :: "r"(a), "r"(cnt) : "memory");
}
__device__ __forceinline__ void mbar_arrive(uint32_t a) {
    asm volatile("mbarrier.arrive.shared.b64 _, [%0];" :: "r"(a) : "memory");
}
__device__ __forceinline__ void mbar_wait(uint32_t a, uint32_t parity) {
    asm volatile(
        "{\n\t"
        ".reg .pred P;\n\t"
        "W_%=:\n\t"
        "mbarrier.try_wait.parity.acquire.cta.shared::cta.b64 P, [%0], %1, 0x989680;\n\t"
        "@P bra D_%=;\n\t"
        "bra W_%=;\n\t"
        "D_%=:\n\t"
        "}" :: "r"(a), "r"(parity) : "memory");
}

__device__ __forceinline__ void ldsm4(uint32_t r[4], uint32_t a) {
    asm volatile("ldmatrix.sync.aligned.m8n8.x4.shared.b16 {%0,%1,%2,%3}, [%4];"
                 : "=r"(r[0]), "=r"(r[1]), "=r"(r[2]), "=r"(r[3]) : "r"(a));
}
__device__ __forceinline__ void ldsm2(uint32_t r[2], uint32_t a) {
    asm volatile("ldmatrix.sync.aligned.m8n8.x2.shared.b16 {%0,%1}, [%2];"
                 : "=r"(r[0]), "=r"(r[1]) : "r"(a));
}
__device__ __forceinline__ void mma16816(float c[4], const uint32_t a[4], const uint32_t b[2]) {
    asm volatile(
        "mma.sync.aligned.m16n8k16.row.col.f32.f16.f16.f32 "
        "{%0,%1,%2,%3}, {%4,%5,%6,%7}, {%8,%9}, {%0,%1,%2,%3};"
        : "+f"(c[0]), "+f"(c[1]), "+f"(c[2]), "+f"(c[3])
        : "r"(a[0]), "r"(a[1]), "r"(a[2]), "r"(a[3]), "r"(b[0]), "r"(b[1]));
}
__device__ __forceinline__ uint32_t h2_u32(__half2 h) {
    return *reinterpret_cast<uint32_t*>(&h);
}

__global__ void __launch_bounds__(256, 2)
qlinear_kernel(const float* __restrict__ x, const uint32_t* __restrict__ qw,
               const float* __restrict__ scales, const float* __restrict__ bias,
               float* __restrict__ out)
{
    extern __shared__ __half sm[];
    const uint32_t smu = (uint32_t)__cvta_generic_to_shared(sm);

    const int tid  = threadIdx.x;
    const int lane = tid & 31;
    const int warp = tid >> 5;
    const int o0   = blockIdx.x * NT;

    // mbarrier layout: full[s] at smu + s*16, empty[s] at +8
    auto fullb  = [&](int s) { return smu + s * 16; };
    auto emptyb = [&](int s) { return smu + s * 16 + 8; };

    if (tid == 0) {
#pragma unroll
        for (int s = 0; s < STAGES; ++s) {
            mbar_init(fullb(s), 128);   // 4 producer warps arrive
            mbar_init(emptyb(s), 128);  // 4 consumer warps arrive
        }
    }
    __syncthreads();

    const uint32_t data0 = smu + DATA_OFF;

    if (warp >= 4) {
        // ================= PRODUCER (warps 4-7, 128 threads) =================
        const int pt = tid - 128;
        const int rb  = pt >> 4;       // row base 0..7
        const int c16 = pt & 15;       // 16B column chunk

        // dtype probe: 0 = int32, 1 = float32
        uint32_t all_int = 1u;
#pragma unroll
        for (int i = 0; i < 8; ++i) {
            uint32_t w = __ldg(qw + i);
            all_int &= ((w + 128u) < 256u) ? 1u : 0u;
        }
        const int mode = all_int ? 0 : 1;

        const uint32_t* wsrc = qw + (size_t)(o0 + rb) * K + c16 * 4;
        const float*    xsrc = x  + (size_t)rb * K + c16 * 4;

        uint4 wA[8], wB[8], xr[4];

        auto ldw = [&](uint4 s[8], int it) {
            const int kc = it * KC;
#pragma unroll
            for (int p = 0; p < 8; ++p)
                s[p] = *reinterpret_cast<const uint4*>(wsrc + (size_t)(p * 8) * K + kc);
        };
        auto ldx = [&](int it) {
            const int kc = it * KC;
#pragma unroll
            for (int p = 0; p < 4; ++p)
                xr[p] = *reinterpret_cast<const uint4*>(
                    reinterpret_cast<const uint32_t*>(xsrc) + (size_t)(p * 8) * K + kc);
        };
        auto sts = [&](const uint4 s[8], int stage) {
            __half* wt = sm + (DATA_OFF / 2) + stage * STAGE_HALVES;
            __half* xt = wt + WT_HALVES;
#pragma unroll
            for (int p = 0; p < 8; ++p) {
                float f0, f1, f2, f3;
                if (mode == 0) {
                    f0 = (float)(int)s[p].x; f1 = (float)(int)s[p].y;
                    f2 = (float)(int)s[p].z; f3 = (float)(int)s[p].w;
                } else {
                    f0 = __uint_as_float(s[p].x); f1 = __uint_as_float(s[p].y);
                    f2 = __uint_as_float(s[p].z); f3 = __uint_as_float(s[p].w);
                }
                *reinterpret_cast<uint2*>(wt + (rb + p * 8) * WTS + c16 * 4) =
                    make_uint2(h2_u32(__floats2half2_rn(f0, f1)),
                               h2_u32(__floats2half2_rn(f2, f3)));
            }
#pragma unroll
            for (int p = 0; p < 4; ++p) {
                float f0 = __uint_as_float(xr[p].x), f1 = __uint_as_float(xr[p].y);
                float f2 = __uint_as_float(xr[p].z), f3 = __uint_as_float(xr[p].w);
                *reinterpret_cast<uint2*>(xt + (rb + p * 8) * WTS + c16 * 4) =
                    make_uint2(h2_u32(__floats2half2_rn(f0, f1)),
                               h2_u32(__floats2half2_rn(f2, f3)));
            }
        };

        int stage = 0, phase = 1;   // fresh empty barriers: parity-1 wait passes immediately
        auto advance = [&]() { if (++stage == STAGES) { stage = 0; phase ^= 1; } };

        ldw(wA, 0);
        for (int it = 0; it < NITER; it += 2) {
            // even: drain wA, prefetch wB
            ldw(wB, it + 1);
            ldx(it);
            mbar_wait(emptyb(stage), phase);
            sts(wA, stage);
            mbar_arrive(fullb(stage));
            advance();
            // odd: drain wB, prefetch wA
            if (it + 2 < NITER) ldw(wA, it + 2);
            ldx(it + 1);
            mbar_wait(emptyb(stage), phase);
            sts(wB, stage);
            mbar_arrive(fullb(stage));
            advance();
        }
        return;  // producers exit
    }

    // ================= CONSUMER (warps 0-3) =================
    const int wn = warp;   // n16 slot

    // ldmatrix lane->address maps (byte offsets within a stage)
    const int rowA  = ((lane >> 3) & 1) * 8 + (lane & 7);
    const int colA  = (lane >> 4) * 8;
    const int laneB = lane & 15;
    const int rowB  = laneB & 7;
    const int colB  = (laneB >> 3) * 8;
    const uint32_t aoff0 = (uint32_t)(WT_HALVES + (0  + rowA) * WTS + colA) * 2;
    const uint32_t aoff1 = (uint32_t)(WT_HALVES + (16 + rowA) * WTS + colA) * 2;
    const uint32_t boff0 = (uint32_t)((wn * 16 + 0 + rowB) * WTS + colB) * 2;
    const uint32_t boff1 = (uint32_t)((wn * 16 + 8 + rowB) * WTS + colB) * 2;

    float acc[2][2][4];
#pragma unroll
    for (int i = 0; i < 2; ++i)
#pragma unroll
        for (int j = 0; j < 2; ++j)
#pragma unroll
            for (int e = 0; e < 4; ++e) acc[i][j][e] = 0.f;

    int stage = 0, phase = 0;
    for (int it = 0; it < NITER; ++it) {
        mbar_wait(fullb(stage), phase);
        const uint32_t base = data0 + (uint32_t)stage * (STAGE_HALVES * 2);
#pragma unroll
        for (int s = 0; s < 4; ++s) {
            const uint32_t koff = (uint32_t)(s * 16) * 2;
            uint32_t a0[4], a1[4], bf0[2], bf1[2];
            ldsm4(a0, base + aoff0 + koff);
            ldsm4(a1, base + aoff1 + koff);
            ldsm2(bf0, base + boff0 + koff);
            ldsm2(bf1, base + boff1 + koff);
            mma16816(acc[0][0], a0, bf0);
            mma16816(acc[0][1], a0, bf1);
            mma16816(acc[1][0], a1, bf0);
            mma16816(acc[1][1], a1, bf1);
        }
        mbar_arrive(emptyb(stage));
        if (++stage == STAGES) { stage = 0; phase ^= 1; }
    }

    // ---- epilogue: each consumer warp owns its full-K n16 slot ----
    const int gm = lane >> 2;
    const int gn = (lane & 3) * 2;
#pragma unroll
    for (int nt = 0; nt < 2; ++nt) {
        const int o = o0 + wn * 16 + nt * 8 + gn;
        const float s0 = scales[o];
        const float s1 = scales[o + 1];
        const float b0 = bias[o];
        const float b1 = bias[o + 1];
#pragma unroll
        for (int mt = 0; mt < 2; ++mt) {
            const float* c = acc[mt][nt];
            const int r0 = mt * 16 + gm;
            float2 v0, v1;
            v0.x = __half2float(__float2half_rn(c[0] * s0 + b0));
            v0.y = __half2float(__float2half_rn(c[1] * s1 + b1));
            v1.x = __half2float(__float2half_rn(c[2] * s0 + b0));
            v1.y = __half2float(__float2half_rn(c[3] * s1 + b1));
            *reinterpret_cast<float2*>(out + (size_t)r0 * N + o) = v0;
            *reinterpret_cast<float2*>(out + (size_t)(r0 + 8) * N + o) = v1;
        }
    }
}

} // anonymous namespace

extern "C" void kernel_launch(void* const* d_in, const int* in_sizes, int n_in,
                              void* d_out, int out_size) {
    const float*    x  = reinterpret_cast<const float*>(d_in[0]);
    const uint32_t* qw = reinterpret_cast<const uint32_t*>(d_in[1]);
    const float*    sc = reinterpret_cast<const float*>(d_in[2]);
    const float*    bi = reinterpret_cast<const float*>(d_in[3]);
    float*          o  = reinterpret_cast<float*>(d_out);

    cudaFuncSetAttribute(qlinear_kernel,
                         cudaFuncAttributeMaxDynamicSharedMemorySize, SMEM_BYTES);
    qlinear_kernel<<<N / NT, 256, SMEM_BYTES>>>(x, qw, sc, bi, o);
}